// round 17
// baseline (speedup 1.0000x reference)
#include <cuda_runtime.h>
#include <cstdint>

#define NN 500
#define GG 128
#define HH 200
#define WW 304
#define HWPX (HH * WW)            // 60800
#define WORDS 1900                // HWPX/32 exact
#define WSTRIDE 1920              // padded bit-row stride (u32), 16B multiple
#define MAXPAIRS (NN * (NN - 1) / 2)
#define MASK_THR 0.005f
#define SIGMA 2.0f

#define NCHUNK 12                 // chunks per mask
#define CHUNKW 160                // words per chunk (last chunk: 140)
#define TOTAL_CTAS (NN * NCHUNK)  // 6000

#define NW 64                     // worker CTAs (last 64 finishers)
#define WCELLS ((NN * NN + NW - 1) / NW)   // 3907 cells per worker slice

// ---- device scratch (zero-init at load; final phase resets per replay) ----
__device__ __align__(16) unsigned int g_bits[NN * WSTRIDE];
__device__ float g_areaf[NN];             // exact small-int float sums: order-invariant
__device__ float g_part[NN * NCHUNK];     // per-(mask,chunk) soft sums, single writer
__device__ float g_comp[NN];              // comp_iou (0 at entry)
__device__ int   g_npairs;                // 0 at entry
__device__ unsigned int g_done;           // decode completion counter (0 at entry)
__device__ unsigned int g_sync1;          // worker phase-A barrier (0 at entry)
__device__ unsigned int g_sync2;          // worker phase-B barrier (0 at entry)
__device__ unsigned int g_pair_ij[MAXPAIRS];
__device__ float g_pair_d[MAXPAIRS];

// process one quad (index k): ballots + predicated sums + lane-0 STG.128
#define PROC(A, B, K) do {                                               \
    const float s0 = (A).x * (B).x, s1 = (A).y * (B).y;                  \
    const float s2 = (A).z * (B).z, s3 = (A).w * (B).w;                  \
    const bool p0 = s0 > MASK_THR, p1 = s1 > MASK_THR;                   \
    const bool p2 = s2 > MASK_THR, p3 = s3 > MASK_THR;                   \
    const unsigned c0 = __ballot_sync(0xffffffffu, p0);                  \
    const unsigned c1 = __ballot_sync(0xffffffffu, p1);                  \
    const unsigned c2 = __ballot_sync(0xffffffffu, p2);                  \
    const unsigned c3 = __ballot_sync(0xffffffffu, p3);                  \
    if (p0) { ssum += s0; areaf += 1.0f; }                               \
    if (p1) { ssum += s1; areaf += 1.0f; }                               \
    if (p2) { ssum += s2; areaf += 1.0f; }                               \
    if (p3) { ssum += s3; areaf += 1.0f; }                               \
    if (lane == 0) pwB[K] = make_uint4(c0, c1, c2, c3);                  \
} while (0)

// ============================================================
// Single fused kernel: decode (R14 form, untouched hot loop) +
// last-64-CTA NMS tail (pair build -> popc -> decay/final).
// All cross-CTA reductions are order-independent, so nondeterministic
// worker identity does not affect the output.
// ============================================================
__global__ __launch_bounds__(256) void solo_kernel(
    const float* __restrict__ segx,
    const float* __restrict__ segy,
    const int* __restrict__ x_inds,
    const int* __restrict__ y_inds,
    const int* __restrict__ labels,
    const float* __restrict__ cate_scores,
    float* __restrict__ out)
{
    const int n    = blockIdx.x / NCHUNK;
    const int c    = blockIdx.x - n * NCHUNK;
    const int tid  = threadIdx.x;
    const int warp = tid >> 5;
    const int lane = tid & 31;

    // -------------------- decode (exact R14 hot loop) --------------------
    {
        const int xi = x_inds[n];
        const int yi = y_inds[n];

        const int w0 = c * CHUNKW;
        const int nquads = ((c == NCHUNK - 1) ? (WORDS - w0) : CHUNKW) >> 2;  // 40 or 35

        const float4* __restrict__ bx =
            reinterpret_cast<const float4*>(segx + (size_t)xi * HWPX) + w0 * 8 + lane;
        const float4* __restrict__ by =
            reinterpret_cast<const float4*>(segy + (size_t)yi * HWPX) + w0 * 8 + lane;
        uint4* pwB = reinterpret_cast<uint4*>(g_bits + n * WSTRIDE + w0);

        float ssum  = 0.0f;
        float areaf = 0.0f;

        int k = warp;
        for (; k + 8 < nquads; k += 16) {
            const float4 a0 = bx[32 * k];
            const float4 b0 = by[32 * k];
            const float4 a1 = bx[32 * (k + 8)];
            const float4 b1 = by[32 * (k + 8)];
            PROC(a0, b0, k);
            PROC(a1, b1, k + 8);
        }
        if (k < nquads) {
            const float4 a0 = bx[32 * k];
            const float4 b0 = by[32 * k];
            PROC(a0, b0, k);
        }

        if (c == NCHUNK - 1 && tid < WSTRIDE - WORDS)
            g_bits[n * WSTRIDE + WORDS + tid] = 0u;

        __shared__ float s_sum[8];
        __shared__ float s_area[8];
#pragma unroll
        for (int off = 16; off > 0; off >>= 1) {
            ssum  += __shfl_down_sync(0xffffffffu, ssum,  off);
            areaf += __shfl_down_sync(0xffffffffu, areaf, off);
        }
        if (lane == 0) { s_sum[warp] = ssum; s_area[warp] = areaf; }
        __syncthreads();
        if (tid == 0) {
            float tsum = 0.0f, tarea = 0.0f;
#pragma unroll
            for (int q = 0; q < 8; q++) { tsum += s_sum[q]; tarea += s_area[q]; }
            g_part[n * NCHUNK + c] = tsum;       // single writer: deterministic
            atomicAdd(&g_areaf[n], tarea);       // exact int-valued float
        }
    }

    // -------------------- completion rank: last NW CTAs become workers ----
    __shared__ int s_widx;
    __syncthreads();
    if (tid == 0) {
        __threadfence();                                  // publish bits/part/area
        unsigned r = atomicAdd(&g_done, 1u) + 1u;         // 1..TOTAL_CTAS
        s_widx = (r > (unsigned)(TOTAL_CTAS - NW)) ? (int)(r - (TOTAL_CTAS - NW) - 1) : -1;
    }
    __syncthreads();
    const int widx = s_widx;
    if (widx < 0) return;

    // wait for ALL decode CTAs (<=63 stragglers remain; slots are free)
    if (tid == 0)
        while (*(volatile unsigned*)&g_done < (unsigned)TOTAL_CTAS) __nanosleep(64);
    __syncthreads();
    __threadfence();                                      // acquire decode writes

    __shared__ int s_lab[NN];
    for (int q = tid; q < NN; q += 256) s_lab[q] = labels[q];
    __syncthreads();

    // ---- phase A: build global pair list from this worker's cell slice ----
    {
        const int lo = widx * WCELLS;
        const int hi = min(lo + WCELLS, NN * NN);
        for (int p = lo + tid; p < hi; p += 256) {
            const int i = p / NN;
            const int j = p - i * NN;
            if (j > i && s_lab[i] == s_lab[j]) {
                int pos = atomicAdd(&g_npairs, 1);
                g_pair_ij[pos] = ((unsigned)i << 16) | (unsigned)j;
            }
        }
    }
    __syncthreads();
    if (tid == 0) {
        __threadfence();
        atomicAdd(&g_sync1, 1u);
        while (*(volatile unsigned*)&g_sync1 < (unsigned)NW) __nanosleep(64);
    }
    __syncthreads();
    __threadfence();

    // ---- phase B: warp-per-pair popcount intersections ----
    const int np = g_npairs;
    for (int q = widx * 8 + warp; q < np; q += NW * 8) {
        const unsigned ij = g_pair_ij[q];
        const int i = (int)(ij >> 16);
        const int j = (int)(ij & 0xffffu);

        const uint4* __restrict__ bi = reinterpret_cast<const uint4*>(g_bits + i * WSTRIDE);
        const uint4* __restrict__ bj = reinterpret_cast<const uint4*>(g_bits + j * WSTRIDE);

        int inter = 0;
#pragma unroll 5
        for (int w = lane; w < WSTRIDE / 4; w += 32) {   // 15 iterations
            uint4 a = bi[w];
            uint4 b = bj[w];
            inter += __popc(a.x & b.x) + __popc(a.y & b.y)
                   + __popc(a.z & b.z) + __popc(a.w & b.w);
        }
#pragma unroll
        for (int off = 16; off > 0; off >>= 1)
            inter += __shfl_down_sync(0xffffffffu, inter, off);

        if (lane == 0) {
            float uni = g_areaf[i] + g_areaf[j] - (float)inter;
            float iou = (float)inter / fmaxf(uni, 1e-6f);
            g_pair_d[q] = iou;
            atomicMax(reinterpret_cast<int*>(&g_comp[j]), __float_as_int(iou)); // iou>=0
        }
    }

    // ---- phase-B barrier: last worker runs the final phase ----
    __shared__ unsigned s_rank2;
    __syncthreads();
    if (tid == 0) {
        __threadfence();
        s_rank2 = atomicAdd(&g_sync2, 1u) + 1u;
    }
    __syncthreads();
    if (s_rank2 != (unsigned)NW) return;
    __threadfence();                                      // acquire phase-B writes

    // -------------------- final phase (one CTA) --------------------
    __shared__ float s_coef[NN];
    __shared__ float s_score[NN];

    for (int m = tid; m < NN; m += 256) {
        float acc = 0.0f;
#pragma unroll
        for (int k = 0; k < NCHUNK; k++) acc += g_part[m * NCHUNK + k];
        s_score[m] = cate_scores[m] * (acc / fmaxf(g_areaf[m], 1.0f));
        s_coef[m] = 1.0f;
    }
    __syncthreads();

    for (int p = tid; p < np; p += 256) {
        const unsigned ij = g_pair_ij[p];
        const int i = (int)(ij >> 16);
        const int j = (int)(ij & 0xffffu);
        const float d = g_pair_d[p];
        const float cc = g_comp[i];
        const float term = __expf(SIGMA * (cc * cc - d * d));   // > 0
        atomicMin(reinterpret_cast<int*>(&s_coef[j]), __float_as_int(term));
    }
    __syncthreads();

    for (int m = tid; m < NN; m += 256) {
        out[m] = s_score[m] * fminf(s_coef[m], 1.0f);
        g_areaf[m] = 0.0f;          // reset for next replay
        g_comp[m]  = 0.0f;
    }
    if (tid == 0) { g_npairs = 0; g_done = 0u; g_sync1 = 0u; g_sync2 = 0u; }
}

extern "C" void kernel_launch(void* const* d_in, const int* in_sizes, int n_in,
                              void* d_out, int out_size)
{
    const float* cate_scores = (const float*)d_in[0];
    const float* segx        = (const float*)d_in[1];
    const float* segy        = (const float*)d_in[2];
    const int*   labels      = (const int*)d_in[3];
    const int*   x_inds      = (const int*)d_in[4];
    const int*   y_inds      = (const int*)d_in[5];
    float* out = (float*)d_out;

    solo_kernel<<<TOTAL_CTAS, 256>>>(segx, segy, x_inds, y_inds,
                                     labels, cate_scores, out);
}